// round 15
// baseline (speedup 1.0000x reference)
#include <cuda_runtime.h>
#include <cstdint>

#define TT   512
#define BB   128
#define NIN  256
#define NH   1024
#define NOUT 32

// ---------------- device scratch ----------------
__device__ unsigned int g_idx[TT * BB * 64];      // per (t,b): up to 256 uint8 indices
__device__ int          g_cnt[TT * BB];
// zbits: word wi = t64*2 + parity; bit p <-> h = t64*64 + 2p + parity
__device__ unsigned int g_zbits[TT * BB * 32];
__device__ float        g_whT[NIN * NH];          // w_h transposed [i][h]

// ---------------- prep: compact (blocks 0..1023) + transpose (blocks 1024..2047) ----------------
__global__ __launch_bounds__(256) void prep_kernel(const float* __restrict__ spikes,
                                                   const float* __restrict__ w_h) {
    if (blockIdx.x >= 1024) {
        int k = (blockIdx.x - 1024) * 256 + threadIdx.x;
        int h = k >> 8;
        int i = k & 255;
        g_whT[i * NH + h] = w_h[k];
        return;
    }

    int gw   = (blockIdx.x * blockDim.x + threadIdx.x) >> 5;
    int lane = threadIdx.x & 31;
    const int NW = 8192;

    for (int u = gw; u < TT * BB; u += NW) {
        const float4* p = (const float4*)(spikes + (size_t)u * NIN) + lane * 2;
        float4 a = __ldcs(p);
        float4 b = __ldcs(p + 1);
        unsigned m8 = 0;
        m8 |= (a.x != 0.f) ? 1u   : 0u;
        m8 |= (a.y != 0.f) ? 2u   : 0u;
        m8 |= (a.z != 0.f) ? 4u   : 0u;
        m8 |= (a.w != 0.f) ? 8u   : 0u;
        m8 |= (b.x != 0.f) ? 16u  : 0u;
        m8 |= (b.y != 0.f) ? 32u  : 0u;
        m8 |= (b.z != 0.f) ? 64u  : 0u;
        m8 |= (b.w != 0.f) ? 128u : 0u;

        int c  = __popc(m8);
        int sc = c;
#pragma unroll
        for (int off = 1; off < 32; off <<= 1) {
            int n = __shfl_up_sync(0xffffffffu, sc, off);
            if (lane >= off) sc += n;
        }
        int tot = __shfl_sync(0xffffffffu, sc, 31);
        int ex  = sc - c;

        unsigned char* outp = (unsigned char*)g_idx + (size_t)u * 256 + ex;
        int base_i = lane << 3;
        unsigned mm = m8;
        int k = 0;
        while (mm) {
            int j = __ffs(mm) - 1; mm &= mm - 1;
            outp[k++] = (unsigned char)(base_i + j);
        }
        if (lane == 31) g_cnt[u] = tot;
    }
}

// ---------------- gather over one 64-h tile: lane owns h-pair via LDS.64 ----------------
// Per-h accumulation chain in increasing index order (bit-identical to R5's per-h sums).
__device__ __forceinline__ void gather64(uint4 q0, uint4 q1, int cnt, size_t tb,
                                         const float2* wrow, float& c0, float& c1) {
    unsigned w8[8] = {q0.x, q0.y, q0.z, q0.w, q1.x, q1.y, q1.z, q1.w};
    int nw = cnt >> 2;
#pragma unroll
    for (int kw = 0; kw < 8; kw++) {
        if (kw >= nw) break;
        unsigned wd = w8[kw];
#pragma unroll
        for (int s = 0; s < 4; s++) {
            float2 f = wrow[((wd >> (8 * s)) & 255u) << 5];
            c0 += f.x; c1 += f.y;
        }
    }
    for (int kw = 8; kw < nw; kw++) {    // rare (>32 actives)
        unsigned wd = g_idx[tb * 64 + kw];
#pragma unroll
        for (int s = 0; s < 4; s++) {
            float2 f = wrow[((wd >> (8 * s)) & 255u) << 5];
            c0 += f.x; c1 += f.y;
        }
    }
    int rem = cnt & 3;
    if (rem) {
        unsigned wd;
        if (nw >= 8) {
            wd = g_idx[tb * 64 + nw];
        } else {
            wd = w8[0];
#pragma unroll
            for (int k = 1; k < 8; k++) if (nw == k) wd = w8[k];
        }
#pragma unroll
        for (int s = 0; s < 3; s++) {
            if (s < rem) {
                float2 f = wrow[((wd >> (8 * s)) & 255u) << 5];
                c0 += f.x; c1 += f.y;
            }
        }
    }
}

// ---------------- fused sparse projection + CUBA LIF scan (147 CTAs, one wave) ----------------
// task64 = (batch, 64-h tile); 2048 tasks; CTA c takes [14c, 14c+14) (last: 4).
// CTA loads the (<=2) 64-h tiles its run spans; warp w runs tasks 14c+2w, +2w+1
// concurrently in one t-loop. Max 14 task64/SM -> 728 crossbar wf/step (vs 832).
#define LIF_SMEM (2 * 256 * 64 * 4)   // two 64KB tile slots

__global__ __launch_bounds__(256) void lif_kernel() {
    extern __shared__ float s_w[];    // slot0 [256][64]; slot1 at +16384 floats
    int tid   = threadIdx.x;
    int c     = blockIdx.x;
    int start = c * 14;
    int size  = 2048 - start; if (size > 14) size = 14;
    int tileA = start >> 7;
    int tileB = (start + size - 1) >> 7;

    // linear conflict-free copy of the two 64-h stripes
    {
        int hA = tileA << 6, hB = tileB << 6;
        for (int k = tid; k < 256 * 64; k += 256) {
            int i = k >> 6, m = k & 63;
            s_w[k]         = g_whT[i * NH + hA + m];
            s_w[16384 + k] = g_whT[i * NH + hB + m];
        }
    }
    __syncthreads();   // only barrier

    int lane = tid & 31;
    int w    = tid >> 5;
    int tAi  = start + 2 * w;
    if (tAi >= start + size) return;
    int  tBi = tAi + 1;
    bool vB  = (tBi < start + size);
    if (!vB) tBi = tAi;                     // alias; results discarded

    int tileTA = tAi >> 7, bA = tAi & 127;
    int tileTB = tBi >> 7, bB = tBi & 127;
    const float2* wrowA = (const float2*)(s_w + (tileTA == tileA ? 0 : 16384)) + lane;
    const float2* wrowB = (const float2*)(s_w + (tileTB == tileA ? 0 : 16384)) + lane;

    size_t tba = (size_t)bA, tbb = (size_t)bB;
    uint4 pa0 = ((const uint4*)(g_idx + tba * 64))[0];
    uint4 pa1 = ((const uint4*)(g_idx + tba * 64))[1];
    int cna = g_cnt[tba];
    uint4 pb0 = ((const uint4*)(g_idx + tbb * 64))[0];
    uint4 pb1 = ((const uint4*)(g_idx + tbb * 64))[1];
    int cnb = g_cnt[tbb];

    float va0 = 0.f, va1 = 0.f, ia0 = 0.f, ia1 = 0.f;
    float vb0 = 0.f, vb1 = 0.f, ib0 = 0.f, ib1 = 0.f;

    for (int t = 0; t < TT; t++) {
        uint4 qa0 = pa0, qa1 = pa1; int ca = cna;
        uint4 qb0 = pb0, qb1 = pb1; int cb = cnb;
        size_t tban = tba + BB, tbbn = tbb + BB;
        if (t + 1 < TT) {                    // prefetch both next lists
            pa0 = ((const uint4*)(g_idx + tban * 64))[0];
            pa1 = ((const uint4*)(g_idx + tban * 64))[1];
            cna = g_cnt[tban];
            pb0 = ((const uint4*)(g_idx + tbbn * 64))[0];
            pb1 = ((const uint4*)(g_idx + tbbn * 64))[1];
            cnb = g_cnt[tbbn];
        }

        float c0 = 0.f, c1 = 0.f, d0 = 0.f, d1 = 0.f;
        gather64(qa0, qa1, ca, tba, wrowA, c0, c1);
        gather64(qb0, qb1, cb, tbb, wrowB, d0, d1);

        // CUBA LIF (exact fp32, mirrors reference op order)
        ia0 = ia0 * 0.875f + c0;  va0 = va0 + 0.125f * (ia0 - va0);
        ia1 = ia1 * 0.875f + c1;  va1 = va1 + 0.125f * (ia1 - va1);
        ib0 = ib0 * 0.875f + d0;  vb0 = vb0 + 0.125f * (ib0 - vb0);
        ib1 = ib1 * 0.875f + d1;  vb1 = vb1 + 0.125f * (ib1 - vb1);
        bool zA0 = (va0 - 1.0f) > 0.0f; if (zA0) va0 = 0.f;
        bool zA1 = (va1 - 1.0f) > 0.0f; if (zA1) va1 = 0.f;
        bool zB0 = (vb0 - 1.0f) > 0.0f; if (zB0) vb0 = 0.f;
        bool zB1 = (vb1 - 1.0f) > 0.0f; if (zB1) vb1 = 0.f;

        unsigned mA0 = __ballot_sync(0xffffffffu, zA0);   // even h of tile A
        unsigned mA1 = __ballot_sync(0xffffffffu, zA1);   // odd  h of tile A
        unsigned mB0 = __ballot_sync(0xffffffffu, zB0);
        unsigned mB1 = __ballot_sync(0xffffffffu, zB1);
        if (lane == 0) {
            *(uint2*)(g_zbits + tba * 32 + (tileTA << 1)) = make_uint2(mA0, mA1);
            if (vB)
                *(uint2*)(g_zbits + tbb * 32 + (tileTB << 1)) = make_uint2(mB0, mB1);
        }

        tba = tban; tbb = tbbn;
    }
}

// ---------------- output currents + fused LI scan (R5 core, permuted-zbits addressing) ----------------
#define COUT_SMEM (NH * 33 * 4 + TT * NOUT * 4)

__global__ __launch_bounds__(1024, 1) void cout_li_kernel(const float* __restrict__ w_o,
                                                          float* __restrict__ out) {
    extern __shared__ float smem[];
    float* s_wT = smem;              // [h*33 + o]
    float* s_c  = smem + NH * 33;    // [t*32 + o]
    int tid = threadIdx.x;

    for (int k = tid; k < NOUT * NH; k += 1024) {
        int o = k >> 10;
        int h = k & 1023;
        s_wT[h * 33 + o] = w_o[k];
    }
    __syncthreads();

    int b = blockIdx.x;
    int warp = tid >> 5, lane = tid & 31;

    for (int t = warp; t < TT; t += 32) {
        unsigned m = g_zbits[((size_t)t * BB + b) * 32 + lane];
        float c0 = 0.f, c1 = 0.f;
#pragma unroll
        for (int wi = 0; wi < 32; wi++) {
            unsigned mw = __shfl_sync(0xffffffffu, m, wi);
            // word wi: t64 = wi>>1, parity = wi&1; bit p <-> h = t64*64 + 2p + parity
            int base = (((wi >> 1) << 6) + (wi & 1)) * 33 + lane;
            while (mw) {
                int p = __ffs(mw) - 1; mw &= mw - 1;
                c0 += s_wT[base + p * 66];
                if (mw) {
                    int p2 = __ffs(mw) - 1; mw &= mw - 1;
                    c1 += s_wT[base + p2 * 66];
                }
            }
        }
        s_c[t * 32 + lane] = c0 + c1;
    }
    __syncthreads();

    // fused CUBA LI readout: warp 0 scans time, lane = output neuron
    if (warp == 0) {
        float v = 0.f, cur = 0.f;
        float cb[4];
#pragma unroll
        for (int j = 0; j < 4; j++) cb[j] = s_c[j * 32 + lane];
        for (int t0 = 0; t0 < TT; t0 += 4) {
            float cn[4];
            if (t0 + 4 < TT) {
#pragma unroll
                for (int j = 0; j < 4; j++) cn[j] = s_c[(t0 + 4 + j) * 32 + lane];
            }
#pragma unroll
            for (int j = 0; j < 4; j++) {
                cur = cur * 0.875f + cb[j];
                v = v + 0.125f * (cur - v);
                out[((size_t)(t0 + j) * BB + b) * 32 + lane] = v;
            }
#pragma unroll
            for (int j = 0; j < 4; j++) cb[j] = cn[j];
        }
    }
}

// ---------------- launch ----------------
extern "C" void kernel_launch(void* const* d_in, const int* in_sizes, int n_in,
                              void* d_out, int out_size) {
    const float* spikes = (const float*)d_in[0];   // [512,128,256]
    const float* w_h    = (const float*)d_in[1];   // [1024,256]
    const float* w_o    = (const float*)d_in[2];   // [32,1024]
    float* out = (float*)d_out;                    // [512,128,32]

    cudaFuncSetAttribute(lif_kernel,     cudaFuncAttributeMaxDynamicSharedMemorySize, LIF_SMEM);
    cudaFuncSetAttribute(cout_li_kernel, cudaFuncAttributeMaxDynamicSharedMemorySize, COUT_SMEM);

    prep_kernel<<<2048, 256>>>(spikes, w_h);
    lif_kernel<<<147, 256, LIF_SMEM>>>();          // 2048 task64s, one wave, <=728 wf/step/SM
    cout_li_kernel<<<BB, 1024, COUT_SMEM>>>(w_o, out);
}

// round 16
// speedup vs baseline: 1.6692x; 1.6692x over previous
#include <cuda_runtime.h>
#include <cstdint>

#define TT   512
#define BB   128
#define NIN  256
#define NH   1024
#define NOUT 32

// ---------------- device scratch ----------------
__device__ unsigned int g_idx[TT * BB * 64];      // per (t,b): up to 256 uint8 indices
__device__ int          g_cnt[TT * BB];
__device__ unsigned int g_zbits[TT * BB * 32];    // word w bit p <-> h = w*32+p (natural)
__device__ float        g_whT[NIN * NH];          // w_h transposed [i][h]

// ---------------- transpose w_h [H][I] -> [I][H] ----------------
__global__ void transpose_wh_kernel(const float* __restrict__ w_h) {
    int k = blockIdx.x * blockDim.x + threadIdx.x;
    if (k < NH * NIN) {
        int h = k >> 8;
        int i = k & 255;
        g_whT[i * NH + h] = w_h[k];
    }
}

// ---------------- compact: warp per (t,b), no smem, no block barrier ----------------
__global__ __launch_bounds__(256) void compact_kernel(const float* __restrict__ spikes) {
    int gw   = (blockIdx.x * blockDim.x + threadIdx.x) >> 5;
    int lane = threadIdx.x & 31;
    const int NW = 8192;   // 1024 blocks * 8 warps

    for (int u = gw; u < TT * BB; u += NW) {
        const float4* p = (const float4*)(spikes + (size_t)u * NIN) + lane * 2;
        float4 a = __ldcs(p);
        float4 b = __ldcs(p + 1);
        unsigned m8 = 0;
        m8 |= (a.x != 0.f) ? 1u   : 0u;
        m8 |= (a.y != 0.f) ? 2u   : 0u;
        m8 |= (a.z != 0.f) ? 4u   : 0u;
        m8 |= (a.w != 0.f) ? 8u   : 0u;
        m8 |= (b.x != 0.f) ? 16u  : 0u;
        m8 |= (b.y != 0.f) ? 32u  : 0u;
        m8 |= (b.z != 0.f) ? 64u  : 0u;
        m8 |= (b.w != 0.f) ? 128u : 0u;

        int c  = __popc(m8);
        int sc = c;
#pragma unroll
        for (int off = 1; off < 32; off <<= 1) {
            int n = __shfl_up_sync(0xffffffffu, sc, off);
            if (lane >= off) sc += n;
        }
        int tot = __shfl_sync(0xffffffffu, sc, 31);
        int ex  = sc - c;

        unsigned char* outp = (unsigned char*)g_idx + (size_t)u * 256 + ex;
        int base_i = lane << 3;
        unsigned mm = m8;
        int k = 0;
        while (mm) {
            int j = __ffs(mm) - 1; mm &= mm - 1;
            outp[k++] = (unsigned char)(base_i + j);
        }
        if (lane == 31) g_cnt[u] = tot;
    }
}

// ---------------- fused sparse projection + CUBA LIF scan ----------------
// Grid (8,16): bx = 128-h tile, by = 8-batch group. Block 256 = 8 warps.
// Warp = (batch, htile); lane owns 4 h via one LDS.128 per active input.
// Permuted tile: s_w[i*128 + lane*4 + j] = whT[i][h0 + 32*j + lane]
//   -> float4 component j maps to h = h0 + 32*j + lane, so ballot(z_j) is
//      exactly natural-layout word (h0/32 + j). smem 128 KB, 1 CTA/SM.
#define LIF_SMEM (NIN * 128 * 4)

__global__ __launch_bounds__(256) void lif_kernel() {
    extern __shared__ float s_w[];
    int tid = threadIdx.x;
    int h0  = blockIdx.x << 7;
    int b0  = blockIdx.y << 3;

    // coalesced read, permuted write (setup-only bank conflicts are fine)
    for (int k = tid; k < NIN * 128; k += 256) {
        int i = k >> 7, m = k & 127;
        float w = g_whT[i * NH + h0 + m];
        s_w[(i << 7) + ((m & 31) << 2) + (m >> 5)] = w;
    }
    __syncthreads();   // only barrier

    int lane = tid & 31;
    int b    = b0 + (tid >> 5);
    const float4* wrow = (const float4*)s_w + lane;

    size_t tb = (size_t)b;
    uint4 p0 = ((const uint4*)(g_idx + tb * 64))[0];
    uint4 p1 = ((const uint4*)(g_idx + tb * 64))[1];
    int cnt_n = g_cnt[tb];

    float v0 = 0.f, v1 = 0.f, v2 = 0.f, v3 = 0.f;
    float i0 = 0.f, i1 = 0.f, i2 = 0.f, i3 = 0.f;

    for (int t = 0; t < TT; t++) {
        uint4 q0 = p0, q1 = p1;
        int cnt = cnt_n;
        size_t tbn = tb + BB;
        if (t + 1 < TT) {                    // prefetch next step's list
            p0 = ((const uint4*)(g_idx + tbn * 64))[0];
            p1 = ((const uint4*)(g_idx + tbn * 64))[1];
            cnt_n = g_cnt[tbn];
        }

        unsigned w8[8] = {q0.x, q0.y, q0.z, q0.w, q1.x, q1.y, q1.z, q1.w};
        int nw = cnt >> 2;

        float c0 = 0.f, c1 = 0.f, c2 = 0.f, c3 = 0.f;  // per-h chains, index order
#pragma unroll
        for (int kw = 0; kw < 8; kw++) {
            if (kw >= nw) break;
            unsigned wd = w8[kw];
#pragma unroll
            for (int s = 0; s < 4; s++) {
                float4 f = wrow[((wd >> (8 * s)) & 255u) << 5];
                c0 += f.x; c1 += f.y; c2 += f.z; c3 += f.w;
            }
        }
        for (int kw = 8; kw < nw; kw++) {    // rare (>32 actives)
            unsigned wd = g_idx[tb * 64 + kw];
#pragma unroll
            for (int s = 0; s < 4; s++) {
                float4 f = wrow[((wd >> (8 * s)) & 255u) << 5];
                c0 += f.x; c1 += f.y; c2 += f.z; c3 += f.w;
            }
        }
        int rem = cnt & 3;
        if (rem) {
            unsigned wd;
            if (nw >= 8) {
                wd = g_idx[tb * 64 + nw];
            } else {
                wd = w8[0];
#pragma unroll
                for (int k = 1; k < 8; k++) if (nw == k) wd = w8[k];
            }
#pragma unroll
            for (int s = 0; s < 3; s++) {
                if (s < rem) {
                    float4 f = wrow[((wd >> (8 * s)) & 255u) << 5];
                    c0 += f.x; c1 += f.y; c2 += f.z; c3 += f.w;
                }
            }
        }

        // CUBA LIF (exact fp32, mirrors reference op order)
        i0 = i0 * 0.875f + c0;  v0 = v0 + 0.125f * (i0 - v0);
        i1 = i1 * 0.875f + c1;  v1 = v1 + 0.125f * (i1 - v1);
        i2 = i2 * 0.875f + c2;  v2 = v2 + 0.125f * (i2 - v2);
        i3 = i3 * 0.875f + c3;  v3 = v3 + 0.125f * (i3 - v3);
        bool z0 = (v0 - 1.0f) > 0.0f; if (z0) v0 = 0.f;
        bool z1 = (v1 - 1.0f) > 0.0f; if (z1) v1 = 0.f;
        bool z2 = (v2 - 1.0f) > 0.0f; if (z2) v2 = 0.f;
        bool z3 = (v3 - 1.0f) > 0.0f; if (z3) v3 = 0.f;

        uint4 mz;
        mz.x = __ballot_sync(0xffffffffu, z0);
        mz.y = __ballot_sync(0xffffffffu, z1);
        mz.z = __ballot_sync(0xffffffffu, z2);
        mz.w = __ballot_sync(0xffffffffu, z3);
        if (lane == 0)
            *(uint4*)(g_zbits + tb * 32 + (blockIdx.x << 2)) = mz;

        tb = tbn;
    }
}

// ---------------- output currents + fused LI scan ----------------
#define COUT_SMEM (NH * 33 * 4 + TT * NOUT * 4)

__global__ __launch_bounds__(1024, 1) void cout_li_kernel(const float* __restrict__ w_o,
                                                          float* __restrict__ out) {
    extern __shared__ float smem[];
    float* s_wT = smem;              // [h*33 + o]
    float* s_c  = smem + NH * 33;    // [t*32 + o]
    int tid = threadIdx.x;

    for (int k = tid; k < NOUT * NH; k += 1024) {
        int o = k >> 10;
        int h = k & 1023;
        s_wT[h * 33 + o] = w_o[k];
    }
    __syncthreads();

    int b = blockIdx.x;
    int warp = tid >> 5, lane = tid & 31;

    for (int t = warp; t < TT; t += 32) {
        unsigned m = g_zbits[((size_t)t * BB + b) * 32 + lane];
        float c0 = 0.f, c1 = 0.f;
#pragma unroll
        for (int wi = 0; wi < 32; wi++) {
            unsigned mw = __shfl_sync(0xffffffffu, m, wi);
            int base = wi * (32 * 33) + lane;
            while (mw) {
                int p = __ffs(mw) - 1; mw &= mw - 1;
                c0 += s_wT[base + p * 33];
                if (mw) {
                    int p2 = __ffs(mw) - 1; mw &= mw - 1;
                    c1 += s_wT[base + p2 * 33];
                }
            }
        }
        s_c[t * 32 + lane] = c0 + c1;
    }
    __syncthreads();

    // fused CUBA LI readout: warp 0 scans time, lane = output neuron
    if (warp == 0) {
        float v = 0.f, cur = 0.f;
        float cb[4];
#pragma unroll
        for (int j = 0; j < 4; j++) cb[j] = s_c[j * 32 + lane];
        for (int t0 = 0; t0 < TT; t0 += 4) {
            float cn[4];
            if (t0 + 4 < TT) {
#pragma unroll
                for (int j = 0; j < 4; j++) cn[j] = s_c[(t0 + 4 + j) * 32 + lane];
            }
#pragma unroll
            for (int j = 0; j < 4; j++) {
                cur = cur * 0.875f + cb[j];
                v = v + 0.125f * (cur - v);
                out[((size_t)(t0 + j) * BB + b) * 32 + lane] = v;
            }
#pragma unroll
            for (int j = 0; j < 4; j++) cb[j] = cn[j];
        }
    }
}

// ---------------- launch ----------------
extern "C" void kernel_launch(void* const* d_in, const int* in_sizes, int n_in,
                              void* d_out, int out_size) {
    const float* spikes = (const float*)d_in[0];   // [512,128,256]
    const float* w_h    = (const float*)d_in[1];   // [1024,256]
    const float* w_o    = (const float*)d_in[2];   // [32,1024]
    float* out = (float*)d_out;                    // [512,128,32]

    cudaFuncSetAttribute(lif_kernel,     cudaFuncAttributeMaxDynamicSharedMemorySize, LIF_SMEM);
    cudaFuncSetAttribute(cout_li_kernel, cudaFuncAttributeMaxDynamicSharedMemorySize, COUT_SMEM);

    transpose_wh_kernel<<<(NH * NIN + 1023) / 1024, 1024>>>(w_h);
    compact_kernel<<<1024, 256>>>(spikes);
    lif_kernel<<<dim3(NH / 128, BB / 8), 256, LIF_SMEM>>>();
    cout_li_kernel<<<BB, 1024, COUT_SMEM>>>(w_o, out);
}

// round 17
// speedup vs baseline: 1.6740x; 1.0028x over previous
#include <cuda_runtime.h>
#include <cstdint>

#define TT   512
#define BB   128
#define NIN  256
#define NH   1024
#define NOUT 32

// ---------------- device scratch ----------------
__device__ unsigned int g_idx[TT * BB * 64];      // per (t,b): up to 256 uint8 indices
__device__ int          g_cnt[TT * BB];
__device__ unsigned int g_zbits[TT * BB * 32];    // word w bit p <-> h = w*32+p (natural)
__device__ float        g_whT[NIN * NH];          // w_h transposed [i][h]

// ---------------- prep: compact (blocks 0..1023) + transpose (blocks 1024..2047) ----------------
// R10-measured 16.5 us; outputs byte-identical to the separate kernels.
__global__ __launch_bounds__(256) void prep_kernel(const float* __restrict__ spikes,
                                                   const float* __restrict__ w_h) {
    if (blockIdx.x >= 1024) {
        int k = (blockIdx.x - 1024) * 256 + threadIdx.x;
        int h = k >> 8;
        int i = k & 255;
        g_whT[i * NH + h] = w_h[k];
        return;
    }

    int gw   = (blockIdx.x * blockDim.x + threadIdx.x) >> 5;
    int lane = threadIdx.x & 31;
    const int NW = 8192;   // 1024 blocks * 8 warps

    for (int u = gw; u < TT * BB; u += NW) {
        const float4* p = (const float4*)(spikes + (size_t)u * NIN) + lane * 2;
        float4 a = __ldcs(p);
        float4 b = __ldcs(p + 1);
        unsigned m8 = 0;
        m8 |= (a.x != 0.f) ? 1u   : 0u;
        m8 |= (a.y != 0.f) ? 2u   : 0u;
        m8 |= (a.z != 0.f) ? 4u   : 0u;
        m8 |= (a.w != 0.f) ? 8u   : 0u;
        m8 |= (b.x != 0.f) ? 16u  : 0u;
        m8 |= (b.y != 0.f) ? 32u  : 0u;
        m8 |= (b.z != 0.f) ? 64u  : 0u;
        m8 |= (b.w != 0.f) ? 128u : 0u;

        int c  = __popc(m8);
        int sc = c;
#pragma unroll
        for (int off = 1; off < 32; off <<= 1) {
            int n = __shfl_up_sync(0xffffffffu, sc, off);
            if (lane >= off) sc += n;
        }
        int tot = __shfl_sync(0xffffffffu, sc, 31);
        int ex  = sc - c;

        unsigned char* outp = (unsigned char*)g_idx + (size_t)u * 256 + ex;
        int base_i = lane << 3;
        unsigned mm = m8;
        int k = 0;
        while (mm) {
            int j = __ffs(mm) - 1; mm &= mm - 1;
            outp[k++] = (unsigned char)(base_i + j);
        }
        if (lane == 31) g_cnt[u] = tot;
    }
}

// ---------------- fused sparse projection + CUBA LIF scan (R5/R16 EXACT) ----------------
// Grid (8,16): bx = 128-h tile, by = 8-batch group. Block 256 = 8 warps.
// Warp = (batch, htile); lane owns 4 h via one LDS.128 per active input.
// Permuted tile: s_w[i*128 + lane*4 + j] = whT[i][h0 + 32*j + lane]
//   -> float4 component j maps to h = h0 + 32*j + lane, so ballot(z_j) is
//      exactly natural-layout word (h0/32 + j). smem 128 KB, 1 CTA/SM.
#define LIF_SMEM (NIN * 128 * 4)

__global__ __launch_bounds__(256) void lif_kernel() {
    extern __shared__ float s_w[];
    int tid = threadIdx.x;
    int h0  = blockIdx.x << 7;
    int b0  = blockIdx.y << 3;

    // coalesced read, permuted write (setup-only bank conflicts are fine)
    for (int k = tid; k < NIN * 128; k += 256) {
        int i = k >> 7, m = k & 127;
        float w = g_whT[i * NH + h0 + m];
        s_w[(i << 7) + ((m & 31) << 2) + (m >> 5)] = w;
    }
    __syncthreads();   // only barrier

    int lane = tid & 31;
    int b    = b0 + (tid >> 5);
    const float4* wrow = (const float4*)s_w + lane;

    size_t tb = (size_t)b;
    uint4 p0 = ((const uint4*)(g_idx + tb * 64))[0];
    uint4 p1 = ((const uint4*)(g_idx + tb * 64))[1];
    int cnt_n = g_cnt[tb];

    float v0 = 0.f, v1 = 0.f, v2 = 0.f, v3 = 0.f;
    float i0 = 0.f, i1 = 0.f, i2 = 0.f, i3 = 0.f;

    for (int t = 0; t < TT; t++) {
        uint4 q0 = p0, q1 = p1;
        int cnt = cnt_n;
        size_t tbn = tb + BB;
        if (t + 1 < TT) {                    // prefetch next step's list
            p0 = ((const uint4*)(g_idx + tbn * 64))[0];
            p1 = ((const uint4*)(g_idx + tbn * 64))[1];
            cnt_n = g_cnt[tbn];
        }

        unsigned w8[8] = {q0.x, q0.y, q0.z, q0.w, q1.x, q1.y, q1.z, q1.w};
        int nw = cnt >> 2;

        float c0 = 0.f, c1 = 0.f, c2 = 0.f, c3 = 0.f;  // per-h chains, index order
#pragma unroll
        for (int kw = 0; kw < 8; kw++) {
            if (kw >= nw) break;
            unsigned wd = w8[kw];
#pragma unroll
            for (int s = 0; s < 4; s++) {
                float4 f = wrow[((wd >> (8 * s)) & 255u) << 5];
                c0 += f.x; c1 += f.y; c2 += f.z; c3 += f.w;
            }
        }
        for (int kw = 8; kw < nw; kw++) {    // rare (>32 actives)
            unsigned wd = g_idx[tb * 64 + kw];
#pragma unroll
            for (int s = 0; s < 4; s++) {
                float4 f = wrow[((wd >> (8 * s)) & 255u) << 5];
                c0 += f.x; c1 += f.y; c2 += f.z; c3 += f.w;
            }
        }
        int rem = cnt & 3;
        if (rem) {
            unsigned wd;
            if (nw >= 8) {
                wd = g_idx[tb * 64 + nw];
            } else {
                wd = w8[0];
#pragma unroll
                for (int k = 1; k < 8; k++) if (nw == k) wd = w8[k];
            }
#pragma unroll
            for (int s = 0; s < 3; s++) {
                if (s < rem) {
                    float4 f = wrow[((wd >> (8 * s)) & 255u) << 5];
                    c0 += f.x; c1 += f.y; c2 += f.z; c3 += f.w;
                }
            }
        }

        // CUBA LIF (exact fp32, mirrors reference op order)
        i0 = i0 * 0.875f + c0;  v0 = v0 + 0.125f * (i0 - v0);
        i1 = i1 * 0.875f + c1;  v1 = v1 + 0.125f * (i1 - v1);
        i2 = i2 * 0.875f + c2;  v2 = v2 + 0.125f * (i2 - v2);
        i3 = i3 * 0.875f + c3;  v3 = v3 + 0.125f * (i3 - v3);
        bool z0 = (v0 - 1.0f) > 0.0f; if (z0) v0 = 0.f;
        bool z1 = (v1 - 1.0f) > 0.0f; if (z1) v1 = 0.f;
        bool z2 = (v2 - 1.0f) > 0.0f; if (z2) v2 = 0.f;
        bool z3 = (v3 - 1.0f) > 0.0f; if (z3) v3 = 0.f;

        uint4 mz;
        mz.x = __ballot_sync(0xffffffffu, z0);
        mz.y = __ballot_sync(0xffffffffu, z1);
        mz.z = __ballot_sync(0xffffffffu, z2);
        mz.w = __ballot_sync(0xffffffffu, z3);
        if (lane == 0)
            *(uint4*)(g_zbits + tb * 32 + (blockIdx.x << 2)) = mz;

        tb = tbn;
    }
}

// ---------------- output currents + fused LI scan (R5/R16 EXACT) ----------------
#define COUT_SMEM (NH * 33 * 4 + TT * NOUT * 4)

__global__ __launch_bounds__(1024, 1) void cout_li_kernel(const float* __restrict__ w_o,
                                                          float* __restrict__ out) {
    extern __shared__ float smem[];
    float* s_wT = smem;              // [h*33 + o]
    float* s_c  = smem + NH * 33;    // [t*32 + o]
    int tid = threadIdx.x;

    for (int k = tid; k < NOUT * NH; k += 1024) {
        int o = k >> 10;
        int h = k & 1023;
        s_wT[h * 33 + o] = w_o[k];
    }
    __syncthreads();

    int b = blockIdx.x;
    int warp = tid >> 5, lane = tid & 31;

    for (int t = warp; t < TT; t += 32) {
        unsigned m = g_zbits[((size_t)t * BB + b) * 32 + lane];
        float c0 = 0.f, c1 = 0.f;
#pragma unroll
        for (int wi = 0; wi < 32; wi++) {
            unsigned mw = __shfl_sync(0xffffffffu, m, wi);
            int base = wi * (32 * 33) + lane;
            while (mw) {
                int p = __ffs(mw) - 1; mw &= mw - 1;
                c0 += s_wT[base + p * 33];
                if (mw) {
                    int p2 = __ffs(mw) - 1; mw &= mw - 1;
                    c1 += s_wT[base + p2 * 33];
                }
            }
        }
        s_c[t * 32 + lane] = c0 + c1;
    }
    __syncthreads();

    // fused CUBA LI readout: warp 0 scans time, lane = output neuron
    if (warp == 0) {
        float v = 0.f, cur = 0.f;
        float cb[4];
#pragma unroll
        for (int j = 0; j < 4; j++) cb[j] = s_c[j * 32 + lane];
        for (int t0 = 0; t0 < TT; t0 += 4) {
            float cn[4];
            if (t0 + 4 < TT) {
#pragma unroll
                for (int j = 0; j < 4; j++) cn[j] = s_c[(t0 + 4 + j) * 32 + lane];
            }
#pragma unroll
            for (int j = 0; j < 4; j++) {
                cur = cur * 0.875f + cb[j];
                v = v + 0.125f * (cur - v);
                out[((size_t)(t0 + j) * BB + b) * 32 + lane] = v;
            }
#pragma unroll
            for (int j = 0; j < 4; j++) cb[j] = cn[j];
        }
    }
}

// ---------------- launch ----------------
extern "C" void kernel_launch(void* const* d_in, const int* in_sizes, int n_in,
                              void* d_out, int out_size) {
    const float* spikes = (const float*)d_in[0];   // [512,128,256]
    const float* w_h    = (const float*)d_in[1];   // [1024,256]
    const float* w_o    = (const float*)d_in[2];   // [32,1024]
    float* out = (float*)d_out;                    // [512,128,32]

    cudaFuncSetAttribute(lif_kernel,     cudaFuncAttributeMaxDynamicSharedMemorySize, LIF_SMEM);
    cudaFuncSetAttribute(cout_li_kernel, cudaFuncAttributeMaxDynamicSharedMemorySize, COUT_SMEM);

    prep_kernel<<<2048, 256>>>(spikes, w_h);       // compact + transpose, one launch
    lif_kernel<<<dim3(NH / 128, BB / 8), 256, LIF_SMEM>>>();
    cout_li_kernel<<<BB, 1024, COUT_SMEM>>>(w_o, out);
}